// round 17
// baseline (speedup 1.0000x reference)
#include <cuda_runtime.h>
#include <cuda_fp16.h>
#include <cstdint>
#include <math.h>

#define DIM    4096
#define B_ROWS 8192
#define EPS    1e-6f

// GEMM tiling: CTA 128x256, 8 warps (2x4 of 64x64 warp tiles)
#define BM 128
#define BN 256
#define BK 32
#define NT 16                 // column tiles (256 wide)
#define MT 64                 // row tiles
#define ROWB 80               // bytes per smem row (32 fp16 = 64B data + 16B pad)
#define TILE_A_B (128 * ROWB)   // 10240 bytes (A tile)
#define TILE_B_B (256 * ROWB)   // 20480 bytes (B tile)
#define STAGE_B (TILE_A_B + TILE_B_B)  // 30720
#define NSTAGE 6
#define DYN_SMEM (NSTAGE * STAGE_B)    // 184320 -> 1 CTA/SM

// merged prologue block split
#define XBLOCKS ((B_ROWS * DIM) / (256 * 4))   // 32768
#define WBLOCKS ((DIM / 32) * (DIM / 32))      // 16384

// ---------------- scratch (device globals; no runtime allocation) ----------
__device__ __half g_xh[(size_t)B_ROWS * DIM];        // fp16-rounded x
__device__ __half g_whT[(size_t)DIM * DIM];          // W^T: [n][k] fp16
__device__ __half g_hh[(size_t)B_ROWS * DIM];        // h stored fp16 (stats from f32)
__device__ float g_psum[128 * DIM];
__device__ float g_psumsq[128 * DIM];
__device__ float g_psum2[8 * DIM];
__device__ float g_psumsq2[8 * DIM];
__device__ float g_mean[DIM];
__device__ float g_scale[DIM];

// ---------------- helpers ---------------------------------------------------
__device__ __forceinline__ uint32_t smem_u32(const void* p) {
    uint32_t a;
    asm("{ .reg .u64 t; cvta.to.shared.u64 t, %1; cvt.u32.u64 %0, t; }"
        : "=r"(a) : "l"(p));
    return a;
}

__device__ __forceinline__ uint32_t pk2(__half a, __half b) {
    return (uint32_t)__half_as_ushort(a) | ((uint32_t)__half_as_ushort(b) << 16);
}

#define CPA16(dst, src) \
    asm volatile("cp.async.cg.shared.global [%0], [%1], 16;" :: "r"(dst), "l"(src) : "memory")
#define CPA_COMMIT() asm volatile("cp.async.commit_group;" ::: "memory")
#define CPA_WAIT4()  asm volatile("cp.async.wait_group 4;" ::: "memory")
#define CPA_WAIT3()  asm volatile("cp.async.wait_group 3;" ::: "memory")
#define CPA_WAIT2()  asm volatile("cp.async.wait_group 2;" ::: "memory")
#define CPA_WAIT1()  asm volatile("cp.async.wait_group 1;" ::: "memory")
#define CPA_WAIT0()  asm volatile("cp.async.wait_group 0;" ::: "memory")

#define LDSM4(r0, r1, r2, r3, addr) \
    asm volatile("ldmatrix.sync.aligned.m8n8.x4.shared.b16 {%0,%1,%2,%3}, [%4];" \
        : "=r"(r0), "=r"(r1), "=r"(r2), "=r"(r3) : "r"(addr))

__device__ __forceinline__ void mma_fp16(float* c, const uint32_t* a, const uint32_t* b) {
    asm volatile(
        "mma.sync.aligned.m16n8k16.row.col.f32.f16.f16.f32 "
        "{%0,%1,%2,%3}, {%4,%5,%6,%7}, {%8,%9}, {%0,%1,%2,%3};"
        : "+f"(c[0]), "+f"(c[1]), "+f"(c[2]), "+f"(c[3])
        : "r"(a[0]), "r"(a[1]), "r"(a[2]), "r"(a[3]),
          "r"(b[0]), "r"(b[1]));
}

// ---------------- merged prologue: x -> fp16 ; W^T (masked, diag^2) -> fp16 -
__global__ __launch_bounds__(256) void prologue_kernel(
    const float4* __restrict__ x,
    const float* __restrict__ tw, const float* __restrict__ bbw)
{
    if (blockIdx.x < XBLOCKS) {
        const size_t i = (size_t)blockIdx.x * 256 + threadIdx.x;
        const float4 v = x[i];
        uint2 H;
        H.x = pk2(__float2half_rn(v.x), __float2half_rn(v.y));
        H.y = pk2(__float2half_rn(v.z), __float2half_rn(v.w));
        ((uint2*)g_xh)[i] = H;
    } else {
        __shared__ float sw[32][33];
        const int bid = blockIdx.x - XBLOCKS;
        const int n0 = (bid & 127) * 32;
        const int k0 = (bid >> 7) * 32;
        const int tx = threadIdx.x & 31;
        const int ty = threadIdx.x >> 5;

        #pragma unroll
        for (int r = 0; r < 4; r++) {
            const int k = k0 + ty + r * 8;
            const int n = n0 + tx;
            const int kb = k >> 6, nb = n >> 6;
            float w = 0.0f;
            if (kb == nb)      { const float t = tw[(size_t)k * DIM + n]; w = t * t; }
            else if (kb < nb)  { w = bbw[(size_t)k * DIM + n]; }
            sw[ty + r * 8][tx] = w;
        }
        __syncthreads();
        #pragma unroll
        for (int r = 0; r < 4; r++) {
            const int n = n0 + ty + r * 8;
            const int k = k0 + tx;
            g_whT[(size_t)n * DIM + k] = __float2half_rn(sw[tx][ty + r * 8]);
        }
    }
}

// ---------------- fp16 GEMM + fused column stats ----------------------------
// Grid (NT, MT). CTA 128x256, 256 threads (8 warps, 2x4 of 64x64 warp tiles).
// BK=32, 6-stage cp.async pipeline (1 sync/k-tile), 1 CTA/SM.
// Warp: m-half = wid>>2 (0..1), n-quarter = wid&3 (0..3).
// Epilogue: h = c + x_init (f32) -> stats (f32) + g_hh (fp16), fixed slots
// g_psum/g_psumsq[rg = mt*2 + (wid>>2)] (same 64-row groups as before).
__global__ __launch_bounds__(256, 1) void gemm_mma_kernel(const float* __restrict__ x_init)
{
    extern __shared__ char smc[];
    const uint32_t smb = smem_u32(smc);

    const int tid = threadIdx.x;
    const int wid = tid >> 5;
    const int lid = tid & 31;
    const int lane4 = lid >> 2;     // 0..7
    const int laneq = lid & 3;      // 0..3

    const int nt = (NT - 1) - blockIdx.x;   // heavy tiles first
    const int mt = blockIdx.y;
    const int m0 = mt * BM;
    const int n0 = nt * BN;
    const int KT = (nt + 1) * 8;    // k-tiles of 32 (>= 8)

    const int m0w = (wid >> 2) * 64;
    const int n0w = (wid & 3) * 64;

    float c[4][8][4];
    #pragma unroll
    for (int i = 0; i < 4; i++)
        #pragma unroll
        for (int j = 0; j < 8; j++)
            #pragma unroll
            for (int q = 0; q < 4; q++)
                c[i][j][q] = 0.0f;

    // producer: 6 cp.async (16B) per thread per stage.
    // idx 0..511 -> A rows 0..127 x 4 chunks; idx 512..1535 -> B rows 0..255 x 4.
    auto issue_stage = [&](int kt, int s) {
        const int kof = kt * BK;
        const uint32_t sb = smb + (uint32_t)s * STAGE_B;
        #pragma unroll
        for (int it = 0; it < 6; it++) {
            const int idx = tid + it * 256;
            if (idx < 512) {
                const int row = idx >> 2;
                const int ch  = idx & 3;
                const __half* src = g_xh + (size_t)(m0 + row) * DIM + kof + ch * 8;
                const uint32_t dst = sb + (uint32_t)(row * ROWB + ch * 16);
                CPA16(dst, src);
            } else {
                const int j2  = idx - 512;
                const int row = j2 >> 2;
                const int ch  = j2 & 3;
                const __half* src = g_whT + (size_t)(n0 + row) * DIM + kof + ch * 8;
                const uint32_t dst = sb + (uint32_t)(TILE_A_B + row * ROWB + ch * 16);
                CPA16(dst, src);
            }
        }
        CPA_COMMIT();
    };

    // per-thread ldmatrix offset components (byte offsets within a tile)
    const int L = lid;
    const uint32_t a_off = (uint32_t)((m0w + (L & 15)) * ROWB + (L >> 4) * 16);
    const uint32_t b_off = (uint32_t)((n0w + ((L >> 4) & 1) * 8 + (L & 7)) * ROWB
                                      + ((L >> 3) & 1) * 16);

    // prologue: fill 5 stages (KT >= 8 always)
    issue_stage(0, 0);
    issue_stage(1, 1);
    issue_stage(2, 2);
    issue_stage(3, 3);
    issue_stage(4, 4);

    int s  = 0;              // stage of k-tile kt
    int s5 = NSTAGE - 1;     // stage of k-tile kt+5
    for (int kt = 0; kt < KT; kt++) {
        // wait until stage kt landed (pending groups = min(KT-kt-1, 4))
        const int rem = KT - kt - 1;
        if      (rem >= 4) { CPA_WAIT4(); }
        else if (rem == 3) { CPA_WAIT3(); }
        else if (rem == 2) { CPA_WAIT2(); }
        else if (rem == 1) { CPA_WAIT1(); }
        else               { CPA_WAIT0(); }
        __syncthreads();

        // refill the slot read at iteration kt-1 (safe behind the sync)
        if (kt + 5 < KT) issue_stage(kt + 5, s5);

        const uint32_t sb  = smb + (uint32_t)s * STAGE_B;
        const uint32_t sAh = sb;
        const uint32_t sBh = sb + TILE_A_B;

        #pragma unroll
        for (int ks = 0; ks < 2; ks++) {
            const uint32_t ko = (uint32_t)ks * 32;

            // all loads first: 4 B-LDSM4 + 4 A-LDSM4
            uint32_t bh[8][2];
            #pragma unroll
            for (int jp = 0; jp < 4; jp++) {
                const uint32_t bo = b_off + (uint32_t)jp * 16 * ROWB + ko;
                LDSM4(bh[jp*2][0], bh[jp*2][1], bh[jp*2+1][0], bh[jp*2+1][1], sBh + bo);
            }
            uint32_t ah[4][4];
            #pragma unroll
            for (int i = 0; i < 4; i++) {
                const uint32_t ao = a_off + (uint32_t)i * 16 * ROWB + ko;
                LDSM4(ah[i][0], ah[i][1], ah[i][2], ah[i][3], sAh + ao);
            }
            #pragma unroll
            for (int i = 0; i < 4; i++)
                #pragma unroll
                for (int j = 0; j < 8; j++)
                    mma_fp16(c[i][j], ah[i], bh[j]);
        }

        s  = (s  == NSTAGE - 1) ? 0 : s  + 1;
        s5 = (s5 == NSTAGE - 1) ? 0 : s5 + 1;
    }

    // ---- epilogue: h = c + x_init (f32); stats in f32; store h as fp16 ----
    float cs[8][2], cq[8][2];
    #pragma unroll
    for (int j = 0; j < 8; j++) {
        cs[j][0] = 0.f; cs[j][1] = 0.f;
        cq[j][0] = 0.f; cq[j][1] = 0.f;
    }

    #pragma unroll
    for (int i = 0; i < 4; i++) {
        const int row = m0 + m0w + i * 16 + lane4;
        #pragma unroll
        for (int j = 0; j < 8; j++) {
            const int col = n0 + n0w + j * 8 + laneq * 2;
            const size_t o0 = (size_t)row * DIM + col;
            const size_t o1 = (size_t)(row + 8) * DIM + col;
            const float2 x0 = *(const float2*)(x_init + o0);
            const float2 x1 = *(const float2*)(x_init + o1);
            float2 v0, v1;
            v0.x = c[i][j][0] + x0.x;
            v0.y = c[i][j][1] + x0.y;
            v1.x = c[i][j][2] + x1.x;
            v1.y = c[i][j][3] + x1.y;
            *(__half2*)(g_hh + o0) = __floats2half2_rn(v0.x, v0.y);
            *(__half2*)(g_hh + o1) = __floats2half2_rn(v1.x, v1.y);
            cs[j][0] += v0.x + v1.x;
            cs[j][1] += v0.y + v1.y;
            cq[j][0] = fmaf(v0.x, v0.x, fmaf(v1.x, v1.x, cq[j][0]));
            cq[j][1] = fmaf(v0.y, v0.y, fmaf(v1.y, v1.y, cq[j][1]));
        }
    }

    // reduce over lane4 (8 lanes: xor 4, 8, 16); then lanes 0..3 write
    const int rg = mt * 2 + (wid >> 2);      // 64-row group id (0..127)
    #pragma unroll
    for (int j = 0; j < 8; j++) {
        #pragma unroll
        for (int b = 0; b < 2; b++) {
            float sv = cs[j][b], qv = cq[j][b];
            sv += __shfl_xor_sync(0xffffffffu, sv, 4);
            sv += __shfl_xor_sync(0xffffffffu, sv, 8);
            sv += __shfl_xor_sync(0xffffffffu, sv, 16);
            qv += __shfl_xor_sync(0xffffffffu, qv, 4);
            qv += __shfl_xor_sync(0xffffffffu, qv, 8);
            qv += __shfl_xor_sync(0xffffffffu, qv, 16);
            if (lane4 == 0) {
                const int col = n0 + n0w + j * 8 + laneq * 2 + b;
                g_psum[rg * DIM + col]   = sv;
                g_psumsq[rg * DIM + col] = qv;
            }
        }
    }
}

// ---------------- stats 2a: reduce 128 row-groups -> 8 ----------------------
__global__ __launch_bounds__(256) void stats2a_kernel()
{
    const int col = blockIdx.x * 256 + threadIdx.x;
    const int g   = blockIdx.y;                    // 0..7
    float s = 0.0f, q = 0.0f;
    #pragma unroll
    for (int r = 0; r < 16; r++) {
        const int rg = g * 16 + r;
        s += g_psum[rg * DIM + col];
        q += g_psumsq[rg * DIM + col];
    }
    g_psum2[g * DIM + col]   = s;
    g_psumsq2[g * DIM + col] = q;
}

// ---------------- stats 2b: finalize mean / scale ---------------------------
__global__ __launch_bounds__(256) void stats2b_kernel()
{
    const int col = blockIdx.x * 256 + threadIdx.x;
    float s = 0.0f, q = 0.0f;
    #pragma unroll
    for (int g = 0; g < 8; g++) {
        s += g_psum2[g * DIM + col];
        q += g_psumsq2[g * DIM + col];
    }
    const float inv_n = 1.0f / (float)B_ROWS;
    const float mean  = s * inv_n;
    float var = q * inv_n - mean * mean;
    var = fmaxf(var, 0.0f);
    g_mean[col]  = mean;
    g_scale[col] = 1.0f / (sqrtf(var) + EPS);
}

// ---------------- normalize + sigmoid (h read as fp16) ----------------------
__global__ __launch_bounds__(256) void final_kernel(float* __restrict__ out)
{
    const int row  = blockIdx.y;
    const int col  = (blockIdx.x * 256 + threadIdx.x) * 4;
    const size_t off = (size_t)row * DIM + col;

    const uint2 raw = *(const uint2*)(g_hh + off);
    const float2 h01 = __half22float2(*(const __half2*)&raw.x);
    const float2 h23 = __half22float2(*(const __half2*)&raw.y);
    const float4 mu = *(const float4*)(g_mean + col);
    const float4 sc = *(const float4*)(g_scale + col);

    float4 o;
    o.x = 1.0f / (1.0f + expf(-(h01.x - mu.x) * sc.x));
    o.y = 1.0f / (1.0f + expf(-(h01.y - mu.y) * sc.y));
    o.z = 1.0f / (1.0f + expf(-(h23.x - mu.z) * sc.z));
    o.w = 1.0f / (1.0f + expf(-(h23.y - mu.w) * sc.w));
    *(float4*)(out + off) = o;
}

// ---------------- launcher ---------------------------------------------------
extern "C" void kernel_launch(void* const* d_in, const int* in_sizes, int n_in,
                              void* d_out, int out_size)
{
    const float* x   = (const float*)d_in[0];
    const float* xi  = (const float*)d_in[1];
    const float* tw  = (const float*)d_in[2];
    const float* bbw = (const float*)d_in[3];
    float* out = (float*)d_out;

    cudaFuncSetAttribute(gemm_mma_kernel,
                         cudaFuncAttributeMaxDynamicSharedMemorySize, DYN_SMEM);

    prologue_kernel<<<XBLOCKS + WBLOCKS, 256>>>((const float4*)x, tw, bbw);
    gemm_mma_kernel<<<dim3(NT, MT), 256, DYN_SMEM>>>(xi);
    stats2a_kernel<<<dim3(16, 8), 256>>>();
    stats2b_kernel<<<16, 256>>>();
    final_kernel<<<dim3(DIM / (256 * 4), B_ROWS), 256>>>(out);
}